// round 6
// baseline (speedup 1.0000x reference)
#include <cuda_runtime.h>

#define NN 512
#define DD 512
#define PP 130816

typedef unsigned long long ull;

__device__ float g_ca[NN*DD];
__device__ float g_cb[NN*DD];
__device__ float g_sa[NN*256];
__device__ float g_sb[NN*256];
__device__ __align__(16) ull g_wp[2560];   // cw2 k-pair packed: [kp][c] = (cw2[2kp][c], cw2[2kp+1][c])

__device__ __forceinline__ ull pack2(float lo, float hi) {
    ull r; asm("mov.b64 %0, {%1, %2};" : "=l"(r) : "f"(lo), "f"(hi)); return r;
}
__device__ __forceinline__ void fma2(ull& d, ull a, ull b) {
    asm("fma.rn.f32x2 %0, %1, %2, %0;" : "+l"(d) : "l"(a), "l"(b));
}
__device__ __forceinline__ float2 unpack2(ull v) {
    float2 f; asm("mov.b64 {%0, %1}, %2;" : "=f"(f.x), "=f"(f.y) : "l"(v)); return f;
}

// ---------------------------------------------------------------------------
// Prep: pack cw2 into k-pair ull table.
// ---------------------------------------------------------------------------
__global__ void prep_kernel(const float* __restrict__ cw2) {
    for (int idx = threadIdx.x; idx < 2560; idx += 512) {
        int kp = idx / 10, c = idx - kp * 10;
        g_wp[idx] = pack2(cw2[kp * 20 + c], cw2[kp * 20 + 10 + c]);
    }
}

// ---------------------------------------------------------------------------
// Phase 1: C = F(512x512) @ B(512 x 1536 concat), BM=64, BN=32, BK=16,
// 128 threads, grid (48,8), DOUBLE-BUFFERED smem.
// ---------------------------------------------------------------------------
__global__ __launch_bounds__(128) void proj_gemm(const float* __restrict__ F,
                                                 const float* __restrict__ cw1,
                                                 const float* __restrict__ sw1) {
    __shared__ __align__(16) float As[2][16 * 68];
    __shared__ __align__(16) ull  Bs[2][16 * 32];
    int t = threadIdx.x;
    int cglob = blockIdx.x * 32;
    const float* Bp; float* Cp; int ldb, bcol;
    if (cglob < 512)       { Bp = cw1;             Cp = g_ca; ldb = 512; bcol = cglob; }
    else if (cglob < 1024) { Bp = cw1 + 512 * 512; Cp = g_cb; ldb = 512; bcol = cglob - 512; }
    else if (cglob < 1280) { Bp = sw1;             Cp = g_sa; ldb = 256; bcol = cglob - 1024; }
    else                   { Bp = sw1 + 512 * 256; Cp = g_sb; ldb = 256; bcol = cglob - 1280; }
    int rb = blockIdx.y * 64;
    int rowg = t & 15, colg = t >> 4;

    int rowA0 = t >> 2, kqA = t & 3;
    int rowA1 = rowA0 + 32;
    int kB = t >> 3, cqB = t & 7;

    ull acc[2][4];
#pragma unroll
    for (int a = 0; a < 2; a++)
#pragma unroll
        for (int b = 0; b < 4; b++) acc[a][b] = 0ull;

    float4 fa0, fa1, fb;
    // prologue fetch + store tile 0
    fa0 = *(const float4*)&F[(rb + rowA0) * 512 + 0 + kqA * 4];
    fa1 = *(const float4*)&F[(rb + rowA1) * 512 + 0 + kqA * 4];
    fb  = *(const float4*)&Bp[(0 + kB) * ldb + bcol + cqB * 4];
    As[0][(kqA * 4 + 0) * 68 + rowA0] = fa0.x;
    As[0][(kqA * 4 + 1) * 68 + rowA0] = fa0.y;
    As[0][(kqA * 4 + 2) * 68 + rowA0] = fa0.z;
    As[0][(kqA * 4 + 3) * 68 + rowA0] = fa0.w;
    As[0][(kqA * 4 + 0) * 68 + rowA1] = fa1.x;
    As[0][(kqA * 4 + 1) * 68 + rowA1] = fa1.y;
    As[0][(kqA * 4 + 2) * 68 + rowA1] = fa1.z;
    As[0][(kqA * 4 + 3) * 68 + rowA1] = fa1.w;
    Bs[0][kB * 32 + cqB * 4 + 0] = pack2(fb.x, fb.x);
    Bs[0][kB * 32 + cqB * 4 + 1] = pack2(fb.y, fb.y);
    Bs[0][kB * 32 + cqB * 4 + 2] = pack2(fb.z, fb.z);
    Bs[0][kB * 32 + cqB * 4 + 3] = pack2(fb.w, fb.w);
    __syncthreads();

    for (int tile = 0; tile < 32; tile++) {
        int cur = tile & 1;
        if (tile < 31) {
            int k0 = (tile + 1) * 16;
            fa0 = *(const float4*)&F[(rb + rowA0) * 512 + k0 + kqA * 4];
            fa1 = *(const float4*)&F[(rb + rowA1) * 512 + k0 + kqA * 4];
            fb  = *(const float4*)&Bp[(k0 + kB) * ldb + bcol + cqB * 4];
        }
#pragma unroll
        for (int k = 0; k < 16; k++) {
            ulonglong2 aA = *(const ulonglong2*)&As[cur][k * 68 + rowg * 4];
            ulonglong2 b0 = *(const ulonglong2*)&Bs[cur][k * 32 + colg * 4];
            ulonglong2 b1 = *(const ulonglong2*)&Bs[cur][k * 32 + colg * 4 + 2];
            fma2(acc[0][0], aA.x, b0.x); fma2(acc[0][1], aA.x, b0.y);
            fma2(acc[0][2], aA.x, b1.x); fma2(acc[0][3], aA.x, b1.y);
            fma2(acc[1][0], aA.y, b0.x); fma2(acc[1][1], aA.y, b0.y);
            fma2(acc[1][2], aA.y, b1.x); fma2(acc[1][3], aA.y, b1.y);
        }
        if (tile < 31) {
            int nxt = cur ^ 1;
            As[nxt][(kqA * 4 + 0) * 68 + rowA0] = fa0.x;
            As[nxt][(kqA * 4 + 1) * 68 + rowA0] = fa0.y;
            As[nxt][(kqA * 4 + 2) * 68 + rowA0] = fa0.z;
            As[nxt][(kqA * 4 + 3) * 68 + rowA0] = fa0.w;
            As[nxt][(kqA * 4 + 0) * 68 + rowA1] = fa1.x;
            As[nxt][(kqA * 4 + 1) * 68 + rowA1] = fa1.y;
            As[nxt][(kqA * 4 + 2) * 68 + rowA1] = fa1.z;
            As[nxt][(kqA * 4 + 3) * 68 + rowA1] = fa1.w;
            Bs[nxt][kB * 32 + cqB * 4 + 0] = pack2(fb.x, fb.x);
            Bs[nxt][kB * 32 + cqB * 4 + 1] = pack2(fb.y, fb.y);
            Bs[nxt][kB * 32 + cqB * 4 + 2] = pack2(fb.z, fb.z);
            Bs[nxt][kB * 32 + cqB * 4 + 3] = pack2(fb.w, fb.w);
        }
        __syncthreads();
    }
#pragma unroll
    for (int mp = 0; mp < 2; mp++) {
        int r = rb + rowg * 4 + mp * 2;
#pragma unroll
        for (int n = 0; n < 4; n++) {
            float2 f = unpack2(acc[mp][n]);
            int c = bcol + colg * 4 + n;
            Cp[r * ldb + c] = f.x;
            Cp[(r + 1) * ldb + c] = f.y;
        }
    }
}

// ---------------------------------------------------------------------------
// Phase 2: tile 16 j x 32 i, 512 threads, 2 blocks/SM (occ 50%).
// Lane -> one (i,j): warp w covers i in {ibase+2w, ibase+2w+1} x 16 j.
// smem: bC 16x516 | aC 32x512 (cb1 folded). Strength restages same memory.
// cw2 pairs read from g_wp via uniform LDG.
// ---------------------------------------------------------------------------
#define O_AC 8256
#define SMEMF 24640

__global__ __launch_bounds__(512, 2) void pair_kernel(
    const float* __restrict__ cb1, const float* __restrict__ cb2,
    const float* __restrict__ sb1, const float* __restrict__ sw2,
    const float* __restrict__ sb2, float* __restrict__ out)
{
    extern __shared__ float sm[];
    int bid = blockIdx.x;
    int jb = 0;
    for (;;) {
        int m = jb + 1;
        int base = (m & 1) ? ((m + 1) / 2) * ((m + 1) / 2) : (m / 2) * (m / 2 + 1);
        if (base <= bid && m < 32) { jb = m; } else if (base <= bid) { jb = m; break; } else break;
    }
    {   // recompute base for jb (loop above may overshoot guard; redo cleanly)
    }
    int base_jb = (jb & 1) ? ((jb + 1) / 2) * ((jb + 1) / 2) : (jb / 2) * (jb / 2 + 1);
    int ib = bid - base_jb;
    int jbase = jb * 16, ibase = ib * 32;
    int t = threadIdx.x;

    // stage bC (16x516) and aC (32x512, +cb1)
#pragma unroll
    for (int it = 0; it < 4; it++) {
        int idx = t + it * 512;
        int r = idx >> 7, q = (idx & 127) * 4;
        *(float4*)&sm[r * 516 + q] = *(const float4*)&g_cb[(jbase + r) * 512 + q];
    }
#pragma unroll
    for (int it = 0; it < 8; it++) {
        int idx = t + it * 512;
        int r = idx >> 7, q = (idx & 127) * 4;
        float4 va = *(const float4*)&g_ca[(ibase + r) * 512 + q];
        float4 vb = *(const float4*)&cb1[q];
        va.x += vb.x; va.y += vb.y; va.z += vb.z; va.w += vb.w;
        *(float4*)&sm[O_AC + r * 512 + q] = va;
    }
    __syncthreads();

    int w = t >> 5, lane = t & 31;
    int jj = lane & 15;
    int iloc = 2 * w + (lane >> 4);
    int i = ibase + iloc;
    int j = jbase + jj;
    const float* bRow = &sm[jj * 516];
    const float* aRow = &sm[O_AC + iloc * 512];
    const ulonglong2* wp2 = (const ulonglong2*)g_wp;

    ull acc[10];
#pragma unroll
    for (int c = 0; c < 10; c++) acc[c] = 0ull;

    for (int k0 = 0; k0 < 512; k0 += 4) {
        float4 bv = *(const float4*)(bRow + k0);
        float4 av = *(const float4*)(aRow + k0);
        float h0 = fmaxf(av.x + bv.x, 0.f);
        float h1 = fmaxf(av.y + bv.y, 0.f);
        float h2 = fmaxf(av.z + bv.z, 0.f);
        float h3 = fmaxf(av.w + bv.w, 0.f);
        ull hp0 = pack2(h0, h1), hp1 = pack2(h2, h3);
        const ulonglong2* wb = wp2 + (k0 >> 1) * 5;
#pragma unroll
        for (int q = 0; q < 5; q++) {
            ulonglong2 wA = wb[q];
            ulonglong2 wB = wb[5 + q];
            fma2(acc[2 * q],     hp0, wA.x);
            fma2(acc[2 * q + 1], hp0, wA.y);
            fma2(acc[2 * q],     hp1, wB.x);
            fma2(acc[2 * q + 1], hp1, wB.y);
        }
    }

    // --- strength path: restage same smem ---
    __syncthreads();
#pragma unroll
    for (int it = 0; it < 2; it++) {
        int idx = t + it * 512;
        int r = idx >> 6, q = (idx & 63) * 4;
        *(float4*)&sm[r * 260 + q] = *(const float4*)&g_sb[(jbase + r) * 256 + q];
    }
#pragma unroll
    for (int it = 0; it < 4; it++) {
        int idx = t + it * 512;
        int r = idx >> 6, q = (idx & 63) * 4;
        float4 va = *(const float4*)&g_sa[(ibase + r) * 256 + q];
        float4 vb = *(const float4*)&sb1[q];
        va.x += vb.x; va.y += vb.y; va.z += vb.z; va.w += vb.w;
        *(float4*)&sm[O_AC + r * 256 + q] = va;
    }
    if (t < 128) ((ull*)&sm[16448])[t] = pack2(sw2[2 * t], sw2[2 * t + 1]);
    __syncthreads();

    ull sacc = 0ull;
    {
        const float* sbRow = &sm[jj * 260];
        const float* saRow = &sm[O_AC + iloc * 256];
        const ull* swp = (const ull*)&sm[16448];
        for (int k0 = 0; k0 < 256; k0 += 4) {
            float4 bv = *(const float4*)(sbRow + k0);
            float4 av = *(const float4*)(saRow + k0);
            float h0 = fmaxf(av.x + bv.x, 0.f);
            float h1 = fmaxf(av.y + bv.y, 0.f);
            float h2 = fmaxf(av.z + bv.z, 0.f);
            float h3 = fmaxf(av.w + bv.w, 0.f);
            fma2(sacc, pack2(h0, h1), swp[k0 >> 1]);
            fma2(sacc, pack2(h2, h3), swp[(k0 >> 1) + 1]);
        }
    }

    if (j > i) {
        float l[10];
#pragma unroll
        for (int c = 0; c < 10; c++) {
            float2 f = unpack2(acc[c]);
            l[c] = f.x + f.y + __ldg(&cb2[c]);
        }
        float m = l[0]; int idx = 0;
#pragma unroll
        for (int c = 1; c < 10; c++) if (l[c] > m) { m = l[c]; idx = c; }
        float sum = 0.f;
#pragma unroll
        for (int c = 0; c < 10; c++) sum += __expf(l[c] - m);
        float lse = m + __logf(sum);
        int p = i * (1023 - i) / 2 + j - i - 1;
        float2* o2 = (float2*)(out + (size_t)p * 10);
#pragma unroll
        for (int q = 0; q < 5; q++)
            o2[q] = make_float2(l[2 * q] - lse, l[2 * q + 1] - lse);
        out[10 * PP + p] = (float)idx;
        float2 fs = unpack2(sacc);
        float x = fs.x + fs.y + __ldg(&sb2[0]);
        out[11 * PP + p] = 1.f / (1.f + __expf(-x));
    }
}

extern "C" void kernel_launch(void* const* d_in, const int* in_sizes, int n_in,
                              void* d_out, int out_size) {
    (void)in_sizes; (void)n_in; (void)out_size;
    const float* features = (const float*)d_in[0];
    const float* cw1 = (const float*)d_in[1];
    const float* cb1 = (const float*)d_in[2];
    const float* cw2 = (const float*)d_in[3];
    const float* cb2 = (const float*)d_in[4];
    const float* sw1 = (const float*)d_in[5];
    const float* sb1 = (const float*)d_in[6];
    const float* sw2 = (const float*)d_in[7];
    const float* sb2 = (const float*)d_in[8];
    float* out = (float*)d_out;

    cudaFuncSetAttribute(pair_kernel, cudaFuncAttributeMaxDynamicSharedMemorySize,
                         SMEMF * sizeof(float));

    prep_kernel<<<1, 512>>>(cw2);
    proj_gemm<<<dim3(48, 8), 128>>>(features, cw1, sw1);
    pair_kernel<<<272, 512, SMEMF * sizeof(float)>>>(
        cb1, cb2, sb1, sw2, sb2, out);
}

// round 7
// speedup vs baseline: 2.1623x; 2.1623x over previous
#include <cuda_runtime.h>

#define NN 512
#define DD 512
#define PP 130816

typedef unsigned long long ull;

__device__ float g_ca[NN*DD];
__device__ float g_cb[NN*DD];
__device__ float g_sa[NN*256];
__device__ float g_sb[NN*256];

__device__ __forceinline__ ull pack2(float lo, float hi) {
    ull r; asm("mov.b64 %0, {%1, %2};" : "=l"(r) : "f"(lo), "f"(hi)); return r;
}
__device__ __forceinline__ void fma2(ull& d, ull a, ull b) {
    asm("fma.rn.f32x2 %0, %1, %2, %0;" : "+l"(d) : "l"(a), "l"(b));
}
__device__ __forceinline__ ull add2(ull a, ull b) {
    ull r; asm("add.rn.f32x2 %0, %1, %2;" : "=l"(r) : "l"(a), "l"(b)); return r;
}
__device__ __forceinline__ float2 unpack2(ull v) {
    float2 f; asm("mov.b64 {%0, %1}, %2;" : "=f"(f.x), "=f"(f.y) : "l"(v)); return f;
}

// ---------------------------------------------------------------------------
// Phase 1: C = F(512x512) @ B(512 x 1536 concat), BM=64, BN=32, BK=16,
// 128 threads, grid (48,8), double-buffered smem.
// ---------------------------------------------------------------------------
__global__ __launch_bounds__(128) void proj_gemm(const float* __restrict__ F,
                                                 const float* __restrict__ cw1,
                                                 const float* __restrict__ sw1) {
    __shared__ __align__(16) float As[2][16 * 68];
    __shared__ __align__(16) ull  Bs[2][16 * 32];
    int t = threadIdx.x;
    int cglob = blockIdx.x * 32;
    const float* Bp; float* Cp; int ldb, bcol;
    if (cglob < 512)       { Bp = cw1;             Cp = g_ca; ldb = 512; bcol = cglob; }
    else if (cglob < 1024) { Bp = cw1 + 512 * 512; Cp = g_cb; ldb = 512; bcol = cglob - 512; }
    else if (cglob < 1280) { Bp = sw1;             Cp = g_sa; ldb = 256; bcol = cglob - 1024; }
    else                   { Bp = sw1 + 512 * 256; Cp = g_sb; ldb = 256; bcol = cglob - 1280; }
    int rb = blockIdx.y * 64;
    int rowg = t & 15, colg = t >> 4;

    int rowA0 = t >> 2, kqA = t & 3;
    int rowA1 = rowA0 + 32;
    int kB = t >> 3, cqB = t & 7;

    ull acc[2][4];
#pragma unroll
    for (int a = 0; a < 2; a++)
#pragma unroll
        for (int b = 0; b < 4; b++) acc[a][b] = 0ull;

    float4 fa0, fa1, fb;
    fa0 = *(const float4*)&F[(rb + rowA0) * 512 + kqA * 4];
    fa1 = *(const float4*)&F[(rb + rowA1) * 512 + kqA * 4];
    fb  = *(const float4*)&Bp[kB * ldb + bcol + cqB * 4];
    As[0][(kqA * 4 + 0) * 68 + rowA0] = fa0.x;
    As[0][(kqA * 4 + 1) * 68 + rowA0] = fa0.y;
    As[0][(kqA * 4 + 2) * 68 + rowA0] = fa0.z;
    As[0][(kqA * 4 + 3) * 68 + rowA0] = fa0.w;
    As[0][(kqA * 4 + 0) * 68 + rowA1] = fa1.x;
    As[0][(kqA * 4 + 1) * 68 + rowA1] = fa1.y;
    As[0][(kqA * 4 + 2) * 68 + rowA1] = fa1.z;
    As[0][(kqA * 4 + 3) * 68 + rowA1] = fa1.w;
    Bs[0][kB * 32 + cqB * 4 + 0] = pack2(fb.x, fb.x);
    Bs[0][kB * 32 + cqB * 4 + 1] = pack2(fb.y, fb.y);
    Bs[0][kB * 32 + cqB * 4 + 2] = pack2(fb.z, fb.z);
    Bs[0][kB * 32 + cqB * 4 + 3] = pack2(fb.w, fb.w);
    __syncthreads();

    for (int tile = 0; tile < 32; tile++) {
        int cur = tile & 1;
        if (tile < 31) {
            int k0 = (tile + 1) * 16;
            fa0 = *(const float4*)&F[(rb + rowA0) * 512 + k0 + kqA * 4];
            fa1 = *(const float4*)&F[(rb + rowA1) * 512 + k0 + kqA * 4];
            fb  = *(const float4*)&Bp[(k0 + kB) * ldb + bcol + cqB * 4];
        }
#pragma unroll
        for (int k = 0; k < 16; k++) {
            ulonglong2 aA = *(const ulonglong2*)&As[cur][k * 68 + rowg * 4];
            ulonglong2 b0 = *(const ulonglong2*)&Bs[cur][k * 32 + colg * 4];
            ulonglong2 b1 = *(const ulonglong2*)&Bs[cur][k * 32 + colg * 4 + 2];
            fma2(acc[0][0], aA.x, b0.x); fma2(acc[0][1], aA.x, b0.y);
            fma2(acc[0][2], aA.x, b1.x); fma2(acc[0][3], aA.x, b1.y);
            fma2(acc[1][0], aA.y, b0.x); fma2(acc[1][1], aA.y, b0.y);
            fma2(acc[1][2], aA.y, b1.x); fma2(acc[1][3], aA.y, b1.y);
        }
        if (tile < 31) {
            int nxt = cur ^ 1;
            As[nxt][(kqA * 4 + 0) * 68 + rowA0] = fa0.x;
            As[nxt][(kqA * 4 + 1) * 68 + rowA0] = fa0.y;
            As[nxt][(kqA * 4 + 2) * 68 + rowA0] = fa0.z;
            As[nxt][(kqA * 4 + 3) * 68 + rowA0] = fa0.w;
            As[nxt][(kqA * 4 + 0) * 68 + rowA1] = fa1.x;
            As[nxt][(kqA * 4 + 1) * 68 + rowA1] = fa1.y;
            As[nxt][(kqA * 4 + 2) * 68 + rowA1] = fa1.z;
            As[nxt][(kqA * 4 + 3) * 68 + rowA1] = fa1.w;
            Bs[nxt][kB * 32 + cqB * 4 + 0] = pack2(fb.x, fb.x);
            Bs[nxt][kB * 32 + cqB * 4 + 1] = pack2(fb.y, fb.y);
            Bs[nxt][kB * 32 + cqB * 4 + 2] = pack2(fb.z, fb.z);
            Bs[nxt][kB * 32 + cqB * 4 + 3] = pack2(fb.w, fb.w);
        }
        __syncthreads();
    }
#pragma unroll
    for (int mp = 0; mp < 2; mp++) {
        int r = rb + rowg * 4 + mp * 2;
#pragma unroll
        for (int n = 0; n < 4; n++) {
            float2 f = unpack2(acc[mp][n]);
            int c = bcol + colg * 4 + n;
            Cp[r * ldb + c] = f.x;
            Cp[(r + 1) * ldb + c] = f.y;
        }
    }
}

// ---------------------------------------------------------------------------
// Phase 2: 1024 threads = 32 warps (occ 50%), tile 32j x 32i, 1 pair/lane.
// warp w -> i = ibase+w (aRow broadcast); lane -> j = jbase+lane.
// smem floats: bC 32x516 | aC 32x512 (+cb1) | w2p 2560 ull.
// Strength path overlays bC/aC/w2p after resync.
// ---------------------------------------------------------------------------
#define O_BC 0
#define O_AC 16512
#define O_WP 32896
#define SMEMF 38016

__global__ __launch_bounds__(1024) void pair_kernel(
    const float* __restrict__ cb1, const float* __restrict__ cw2,
    const float* __restrict__ cb2, const float* __restrict__ sb1,
    const float* __restrict__ sw2, const float* __restrict__ sb2,
    float* __restrict__ out)
{
    extern __shared__ float sm[];
    int bid = blockIdx.x;
    int jb = (int)((sqrtf(8.0f * bid + 1.0f) - 1.0f) * 0.5f);
    while ((jb + 1) * (jb + 2) / 2 <= bid) jb++;
    while (jb * (jb + 1) / 2 > bid) jb--;
    int ib = bid - jb * (jb + 1) / 2;
    int jbase = jb * 32, ibase = ib * 32;
    int t = threadIdx.x;

    // stage bC (32x516), aC (32x512 + cb1), w2p
#pragma unroll
    for (int it = 0; it < 4; it++) {
        int idx = t + it * 1024;
        int r = idx >> 7, q = (idx & 127) * 4;
        *(float4*)&sm[O_BC + r * 516 + q] = *(const float4*)&g_cb[(jbase + r) * 512 + q];
    }
#pragma unroll
    for (int it = 0; it < 4; it++) {
        int idx = t + it * 1024;
        int r = idx >> 7, q = (idx & 127) * 4;
        float4 va = *(const float4*)&g_ca[(ibase + r) * 512 + q];
        float4 vb = *(const float4*)&cb1[q];
        va.x += vb.x; va.y += vb.y; va.z += vb.z; va.w += vb.w;
        *(float4*)&sm[O_AC + r * 512 + q] = va;
    }
    {
        ull* wp = (ull*)&sm[O_WP];
        for (int idx = t; idx < 2560; idx += 1024) {
            int kp = idx / 10, c = idx - kp * 10;
            wp[idx] = pack2(cw2[kp * 20 + c], cw2[kp * 20 + 10 + c]);
        }
    }
    __syncthreads();

    int w = t >> 5, lane = t & 31;
    int i = ibase + w;
    int j = jbase + lane;
    const float* bRow = &sm[O_BC + lane * 516];
    const float* aRow = &sm[O_AC + w * 512];
    const ull*   wp   = (const ull*)&sm[O_WP];

    ull acc[10];
#pragma unroll
    for (int c = 0; c < 10; c++) acc[c] = 0ull;

    for (int k0 = 0; k0 < 512; k0 += 4) {
        ulonglong2 b2 = *(const ulonglong2*)(bRow + k0);
        ulonglong2 a2 = *(const ulonglong2*)(aRow + k0);
        ull s0 = add2(a2.x, b2.x), s1 = add2(a2.y, b2.y);
        float2 f0 = unpack2(s0), f1 = unpack2(s1);
        ull hp0 = pack2(fmaxf(f0.x, 0.f), fmaxf(f0.y, 0.f));
        ull hp1 = pack2(fmaxf(f1.x, 0.f), fmaxf(f1.y, 0.f));
        const ulonglong2* w0 = (const ulonglong2*)(wp + (k0 >> 1) * 10);
        const ulonglong2* w1 = (const ulonglong2*)(wp + (k0 >> 1) * 10 + 10);
#pragma unroll
        for (int q = 0; q < 5; q++) {
            ulonglong2 wA = w0[q];
            ulonglong2 wB = w1[q];
            fma2(acc[2 * q],     hp0, wA.x);
            fma2(acc[2 * q + 1], hp0, wA.y);
            fma2(acc[2 * q],     hp1, wB.x);
            fma2(acc[2 * q + 1], hp1, wB.y);
        }
    }

    // --- strength path: overlay same smem ---
    __syncthreads();
#pragma unroll
    for (int it = 0; it < 2; it++) {
        int idx = t + it * 1024;
        int r = idx >> 6, q = (idx & 63) * 4;
        *(float4*)&sm[O_BC + r * 260 + q] = *(const float4*)&g_sb[(jbase + r) * 256 + q];
    }
#pragma unroll
    for (int it = 0; it < 2; it++) {
        int idx = t + it * 1024;
        int r = idx >> 6, q = (idx & 63) * 4;
        float4 va = *(const float4*)&g_sa[(ibase + r) * 256 + q];
        float4 vb = *(const float4*)&sb1[q];
        va.x += vb.x; va.y += vb.y; va.z += vb.z; va.w += vb.w;
        *(float4*)&sm[O_AC + r * 256 + q] = va;
    }
    if (t < 128) ((ull*)&sm[O_WP])[t] = pack2(sw2[2 * t], sw2[2 * t + 1]);
    __syncthreads();

    ull sacc = 0ull;
    {
        const float* sbRow = &sm[O_BC + lane * 260];
        const float* saRow = &sm[O_AC + w * 256];
        const ull* swp = (const ull*)&sm[O_WP];
        for (int k0 = 0; k0 < 256; k0 += 4) {
            ulonglong2 b2 = *(const ulonglong2*)(sbRow + k0);
            ulonglong2 a2 = *(const ulonglong2*)(saRow + k0);
            ulonglong2 ww = *(const ulonglong2*)(swp + (k0 >> 1));
            ull s0 = add2(a2.x, b2.x), s1 = add2(a2.y, b2.y);
            float2 f0 = unpack2(s0), f1 = unpack2(s1);
            fma2(sacc, pack2(fmaxf(f0.x, 0.f), fmaxf(f0.y, 0.f)), ww.x);
            fma2(sacc, pack2(fmaxf(f1.x, 0.f), fmaxf(f1.y, 0.f)), ww.y);
        }
    }

    if (j > i) {
        float l[10];
#pragma unroll
        for (int c = 0; c < 10; c++) {
            float2 f = unpack2(acc[c]);
            l[c] = f.x + f.y + __ldg(&cb2[c]);
        }
        float m = l[0]; int idx = 0;
#pragma unroll
        for (int c = 1; c < 10; c++) if (l[c] > m) { m = l[c]; idx = c; }
        float sum = 0.f;
#pragma unroll
        for (int c = 0; c < 10; c++) sum += __expf(l[c] - m);
        float lse = m + __logf(sum);
        int p = i * (1023 - i) / 2 + j - i - 1;
        float2* o2 = (float2*)(out + (size_t)p * 10);
#pragma unroll
        for (int q = 0; q < 5; q++)
            o2[q] = make_float2(l[2 * q] - lse, l[2 * q + 1] - lse);
        out[10 * PP + p] = (float)idx;
        float2 fs = unpack2(sacc);
        float x = fs.x + fs.y + __ldg(&sb2[0]);
        out[11 * PP + p] = 1.f / (1.f + __expf(-x));
    }
}

extern "C" void kernel_launch(void* const* d_in, const int* in_sizes, int n_in,
                              void* d_out, int out_size) {
    (void)in_sizes; (void)n_in; (void)out_size;
    const float* features = (const float*)d_in[0];
    const float* cw1 = (const float*)d_in[1];
    const float* cb1 = (const float*)d_in[2];
    const float* cw2 = (const float*)d_in[3];
    const float* cb2 = (const float*)d_in[4];
    const float* sw1 = (const float*)d_in[5];
    const float* sb1 = (const float*)d_in[6];
    const float* sw2 = (const float*)d_in[7];
    const float* sb2 = (const float*)d_in[8];
    float* out = (float*)d_out;

    cudaFuncSetAttribute(pair_kernel, cudaFuncAttributeMaxDynamicSharedMemorySize,
                         SMEMF * sizeof(float));

    proj_gemm<<<dim3(48, 8), 128>>>(features, cw1, sw1);
    pair_kernel<<<136, 1024, SMEMF * sizeof(float)>>>(
        cb1, cw2, cb2, sb1, sw2, sb2, out);
}

// round 8
// speedup vs baseline: 2.6630x; 1.2316x over previous
#include <cuda_runtime.h>

#define NN 512
#define PP 130816
typedef unsigned long long ull;

__device__ float g_ca[NN*512];
__device__ float g_cb[NN*512];
__device__ float g_sa[NN*256];
__device__ float g_sb[NN*256];

__device__ __forceinline__ ull pack2(float lo, float hi) {
    ull r; asm("mov.b64 %0, {%1, %2};" : "=l"(r) : "f"(lo), "f"(hi)); return r;
}
__device__ __forceinline__ void fma2(ull& d, ull a, ull b) {
    asm("fma.rn.f32x2 %0, %1, %2, %0;" : "+l"(d) : "l"(a), "l"(b));
}
__device__ __forceinline__ ull add2(ull a, ull b) {
    ull r; asm("add.rn.f32x2 %0, %1, %2;" : "=l"(r) : "l"(a), "l"(b)); return r;
}
__device__ __forceinline__ float2 unpack2(ull v) {
    float2 f; asm("mov.b64 {%0, %1}, %2;" : "=f"(f.x), "=f"(f.y) : "l"(v)); return f;
}

// ---------------------------------------------------------------------------
// Phase 1: C = F(512x512) @ B(512 x 1536 concat). BM=64, BN=32, BK=32,
// 128 threads, grid (48,8), double-buffered (prefetch window > LDG latency).
// B staged duplicated as (b,b) ulls; A staged transposed.
// ---------------------------------------------------------------------------
__global__ __launch_bounds__(128) void proj_gemm(const float* __restrict__ F,
                                                 const float* __restrict__ cw1,
                                                 const float* __restrict__ sw1) {
    __shared__ __align__(16) float As[2][32 * 68];
    __shared__ __align__(16) ull  Bs[2][32 * 32];
    int t = threadIdx.x;
    int cglob = blockIdx.x * 32;
    const float* Bp; float* Cp; int ldb, bcol;
    if (cglob < 512)       { Bp = cw1;             Cp = g_ca; ldb = 512; bcol = cglob; }
    else if (cglob < 1024) { Bp = cw1 + 512 * 512; Cp = g_cb; ldb = 512; bcol = cglob - 512; }
    else if (cglob < 1280) { Bp = sw1;             Cp = g_sa; ldb = 256; bcol = cglob - 1024; }
    else                   { Bp = sw1 + 512 * 256; Cp = g_sb; ldb = 256; bcol = cglob - 1280; }
    int rb = blockIdx.y * 64;
    int rowg = t & 15, colg = t >> 4;

    ull acc[2][4];
#pragma unroll
    for (int a = 0; a < 2; a++)
#pragma unroll
        for (int b = 0; b < 4; b++) acc[a][b] = 0ull;

    float4 pa[4], pb[2];
#pragma unroll
    for (int it = 0; it < 4; it++) {
        int idx = t + it * 128, row = idx >> 3, q8 = idx & 7;
        pa[it] = *(const float4*)&F[(rb + row) * 512 + q8 * 4];
    }
#pragma unroll
    for (int it = 0; it < 2; it++) {
        int idx = t + it * 128, k = idx >> 3, q8 = idx & 7;
        pb[it] = *(const float4*)&Bp[k * ldb + bcol + q8 * 4];
    }
#pragma unroll
    for (int it = 0; it < 4; it++) {
        int idx = t + it * 128, row = idx >> 3, q8 = idx & 7;
        As[0][(q8 * 4 + 0) * 68 + row] = pa[it].x;
        As[0][(q8 * 4 + 1) * 68 + row] = pa[it].y;
        As[0][(q8 * 4 + 2) * 68 + row] = pa[it].z;
        As[0][(q8 * 4 + 3) * 68 + row] = pa[it].w;
    }
#pragma unroll
    for (int it = 0; it < 2; it++) {
        int idx = t + it * 128, k = idx >> 3, q8 = idx & 7;
        Bs[0][k * 32 + q8 * 4 + 0] = pack2(pb[it].x, pb[it].x);
        Bs[0][k * 32 + q8 * 4 + 1] = pack2(pb[it].y, pb[it].y);
        Bs[0][k * 32 + q8 * 4 + 2] = pack2(pb[it].z, pb[it].z);
        Bs[0][k * 32 + q8 * 4 + 3] = pack2(pb[it].w, pb[it].w);
    }
    __syncthreads();

    for (int tile = 0; tile < 16; tile++) {
        int cur = tile & 1;
        if (tile < 15) {
            int k0 = (tile + 1) * 32;
#pragma unroll
            for (int it = 0; it < 4; it++) {
                int idx = t + it * 128, row = idx >> 3, q8 = idx & 7;
                pa[it] = *(const float4*)&F[(rb + row) * 512 + k0 + q8 * 4];
            }
#pragma unroll
            for (int it = 0; it < 2; it++) {
                int idx = t + it * 128, k = idx >> 3, q8 = idx & 7;
                pb[it] = *(const float4*)&Bp[(k0 + k) * ldb + bcol + q8 * 4];
            }
        }
#pragma unroll
        for (int k = 0; k < 32; k++) {
            ulonglong2 aA = *(const ulonglong2*)&As[cur][k * 68 + rowg * 4];
            ulonglong2 b0 = *(const ulonglong2*)&Bs[cur][k * 32 + colg * 4];
            ulonglong2 b1 = *(const ulonglong2*)&Bs[cur][k * 32 + colg * 4 + 2];
            fma2(acc[0][0], aA.x, b0.x); fma2(acc[0][1], aA.x, b0.y);
            fma2(acc[0][2], aA.x, b1.x); fma2(acc[0][3], aA.x, b1.y);
            fma2(acc[1][0], aA.y, b0.x); fma2(acc[1][1], aA.y, b0.y);
            fma2(acc[1][2], aA.y, b1.x); fma2(acc[1][3], aA.y, b1.y);
        }
        if (tile < 15) {
            int nxt = cur ^ 1;
#pragma unroll
            for (int it = 0; it < 4; it++) {
                int idx = t + it * 128, row = idx >> 3, q8 = idx & 7;
                As[nxt][(q8 * 4 + 0) * 68 + row] = pa[it].x;
                As[nxt][(q8 * 4 + 1) * 68 + row] = pa[it].y;
                As[nxt][(q8 * 4 + 2) * 68 + row] = pa[it].z;
                As[nxt][(q8 * 4 + 3) * 68 + row] = pa[it].w;
            }
#pragma unroll
            for (int it = 0; it < 2; it++) {
                int idx = t + it * 128, k = idx >> 3, q8 = idx & 7;
                Bs[nxt][k * 32 + q8 * 4 + 0] = pack2(pb[it].x, pb[it].x);
                Bs[nxt][k * 32 + q8 * 4 + 1] = pack2(pb[it].y, pb[it].y);
                Bs[nxt][k * 32 + q8 * 4 + 2] = pack2(pb[it].z, pb[it].z);
                Bs[nxt][k * 32 + q8 * 4 + 3] = pack2(pb[it].w, pb[it].w);
            }
        }
        __syncthreads();
    }
#pragma unroll
    for (int mp = 0; mp < 2; mp++) {
        int r = rb + rowg * 4 + mp * 2;
#pragma unroll
        for (int n = 0; n < 4; n++) {
            float2 f = unpack2(acc[mp][n]);
            int c = bcol + colg * 4 + n;
            Cp[r * ldb + c] = f.x;
            Cp[(r + 1) * ldb + c] = f.y;
        }
    }
}

// ---------------------------------------------------------------------------
// Phase 2: tile 32j x 32i, 1024 threads = 32 warps (occ 50%), K-SPLIT:
// warps 0-15 (half=0) k<256, warps 16-31 (half=1) k>=256, same pairs.
// Warp group wg covers i = ibase+2wg, +1 (2 pairs/lane); lane = j.
// Class-paired accumulators: acc0[q]=(logit_{2q}, logit_{2q+1}) for i0, acc1 for i1.
// smem floats: bC 32x516 (cb1 folded) | aC [16][512][2] | w2 [512][12 pad].
// Strength overlays same regions; k-half reduction via smem at the end.
// ---------------------------------------------------------------------------
#define O_BC 0
#define O_AC 16512
#define O_WC 32896
#define SMEMF 39040

__global__ __launch_bounds__(1024) void pair_kernel(
    const float* __restrict__ cb1, const float* __restrict__ cw2,
    const float* __restrict__ cb2, const float* __restrict__ sb1,
    const float* __restrict__ sw2, const float* __restrict__ sb2,
    float* __restrict__ out)
{
    extern __shared__ float sm[];
    int bid = blockIdx.x;
    int jb = (int)((sqrtf(8.0f * bid + 1.0f) - 1.0f) * 0.5f);
    while ((jb + 1) * (jb + 2) / 2 <= bid) jb++;
    while (jb * (jb + 1) / 2 > bid) jb--;
    int ib = bid - jb * (jb + 1) / 2;
    int jbase = jb * 32, ibase = ib * 32;
    int t = threadIdx.x;
    int w = t >> 5, lane = t & 31;
    int wg = w & 15, half = w >> 4;

    // ---- stage classifier tables ----
#pragma unroll
    for (int it = 0; it < 4; it++) {          // bC rows (+cb1)
        int idx = t + it * 1024;
        int r = idx >> 7, q = (idx & 127) * 4;
        float4 vb = *(const float4*)&g_cb[(jbase + r) * 512 + q];
        float4 vc = *(const float4*)&cb1[q];
        vb.x += vc.x; vb.y += vc.y; vb.z += vc.z; vb.w += vc.w;
        *(float4*)&sm[O_BC + r * 516 + q] = vb;
    }
#pragma unroll
    for (int it = 0; it < 4; it++) {          // aC interleaved [wg][k][2]
        int idx = t + it * 1024;
        int r = idx >> 7, q = (idx & 127) * 4;
        float4 va = *(const float4*)&g_ca[(ibase + r) * 512 + q];
        float* dst = &sm[O_AC + (r >> 1) * 1024 + q * 2 + (r & 1)];
        dst[0] = va.x; dst[2] = va.y; dst[4] = va.z; dst[6] = va.w;
    }
    for (int idx = t; idx < 5120; idx += 1024) {   // w2 rows padded to 12
        int k = idx / 10, c = idx - k * 10;
        sm[O_WC + k * 12 + c] = cw2[idx];
    }
    __syncthreads();

    int j = jbase + lane;
    const float* bRow = &sm[O_BC + lane * 516];
    const float* aP   = &sm[O_AC + wg * 1024];

    ull acc0[5], acc1[5];
#pragma unroll
    for (int q = 0; q < 5; q++) { acc0[q] = 0ull; acc1[q] = 0ull; }

    int koff = half * 256;
    for (int k0 = koff; k0 < koff + 256; k0 += 4) {
        float4 bv = *(const float4*)(bRow + k0);
        ulonglong2 aA = *(const ulonglong2*)(aP + 2 * k0);
        ulonglong2 aB = *(const ulonglong2*)(aP + 2 * k0 + 4);
        ull ap[4] = {aA.x, aA.y, aB.x, aB.y};
        float bf[4] = {bv.x, bv.y, bv.z, bv.w};
#pragma unroll
        for (int kk = 0; kk < 4; kk++) {
            ull s = add2(ap[kk], pack2(bf[kk], bf[kk]));
            float2 f = unpack2(s);
            float h0 = fmaxf(f.x, 0.f), h1 = fmaxf(f.y, 0.f);
            ull hh0 = pack2(h0, h0), hh1 = pack2(h1, h1);
            const float* wr = &sm[O_WC + (k0 + kk) * 12];
            ulonglong2 w01 = *(const ulonglong2*)wr;
            ulonglong2 w23 = *(const ulonglong2*)(wr + 4);
            ull w4 = *(const ull*)(wr + 8);
            fma2(acc0[0], hh0, w01.x); fma2(acc0[1], hh0, w01.y);
            fma2(acc0[2], hh0, w23.x); fma2(acc0[3], hh0, w23.y);
            fma2(acc0[4], hh0, w4);
            fma2(acc1[0], hh1, w01.x); fma2(acc1[1], hh1, w01.y);
            fma2(acc1[2], hh1, w23.x); fma2(acc1[3], hh1, w23.y);
            fma2(acc1[4], hh1, w4);
        }
    }

    // ---- strength path: overlay same smem ----
    __syncthreads();
#pragma unroll
    for (int it = 0; it < 2; it++) {          // bS rows (+sb1), 32x260
        int idx = t + it * 1024;
        int r = idx >> 6, q = (idx & 63) * 4;
        float4 vb = *(const float4*)&g_sb[(jbase + r) * 256 + q];
        float4 vc = *(const float4*)&sb1[q];
        vb.x += vc.x; vb.y += vc.y; vb.z += vc.z; vb.w += vc.w;
        *(float4*)&sm[O_BC + r * 260 + q] = vb;
    }
#pragma unroll
    for (int it = 0; it < 2; it++) {          // aS interleaved [wg][k][2]
        int idx = t + it * 1024;
        int r = idx >> 6, q = (idx & 63) * 4;
        float4 va = *(const float4*)&g_sa[(ibase + r) * 256 + q];
        float* dst = &sm[O_AC + (r >> 1) * 512 + q * 2 + (r & 1)];
        dst[0] = va.x; dst[2] = va.y; dst[4] = va.z; dst[6] = va.w;
    }
    if (t < 256) sm[O_WC + t] = sw2[t];
    __syncthreads();

    float s0 = 0.f, s1 = 0.f;
    {
        const float* sbRow = &sm[O_BC + lane * 260];
        const float* saP   = &sm[O_AC + wg * 512];
        int koff2 = half * 128;
        for (int k0 = koff2; k0 < koff2 + 128; k0 += 4) {
            float4 bv = *(const float4*)(sbRow + k0);
            ulonglong2 aA = *(const ulonglong2*)(saP + 2 * k0);
            ulonglong2 aB = *(const ulonglong2*)(saP + 2 * k0 + 4);
            float4 wv = *(const float4*)&sm[O_WC + k0];
            ull ap[4] = {aA.x, aA.y, aB.x, aB.y};
            float bf[4] = {bv.x, bv.y, bv.z, bv.w};
            float wf[4] = {wv.x, wv.y, wv.z, wv.w};
#pragma unroll
            for (int kk = 0; kk < 4; kk++) {
                ull s = add2(ap[kk], pack2(bf[kk], bf[kk]));
                float2 f = unpack2(s);
                s0 = fmaf(fmaxf(f.x, 0.f), wf[kk], s0);
                s1 = fmaf(fmaxf(f.y, 0.f), wf[kk], s1);
            }
        }
    }

    // ---- k-half reduction ----
    __syncthreads();
    ull* red = (ull*)&sm[O_AC];
    int rbase = (wg * 11) * 32 + lane;
    if (half == 1) {
#pragma unroll
        for (int q = 0; q < 5; q++) {
            red[rbase + q * 32] = acc0[q];
            red[rbase + (5 + q) * 32] = acc1[q];
        }
        red[rbase + 10 * 32] = pack2(s0, s1);
    }
    __syncthreads();

    if (half == 0) {
#pragma unroll
        for (int q = 0; q < 5; q++) {
            acc0[q] = add2(acc0[q], red[rbase + q * 32]);
            acc1[q] = add2(acc1[q], red[rbase + (5 + q) * 32]);
        }
        float2 rs = unpack2(red[rbase + 10 * 32]);
        s0 += rs.x; s1 += rs.y;

        float b2[10];
#pragma unroll
        for (int c = 0; c < 10; c++) b2[c] = __ldg(&cb2[c]);
        float sbv = __ldg(&sb2[0]);
        float sv[2] = {s0, s1};
#pragma unroll
        for (int s = 0; s < 2; s++) {
            int i = ibase + 2 * wg + s;
            if (j <= i) continue;
            float l[10];
#pragma unroll
            for (int q = 0; q < 5; q++) {
                float2 f = unpack2(s ? acc1[q] : acc0[q]);
                l[2 * q] = f.x + b2[2 * q];
                l[2 * q + 1] = f.y + b2[2 * q + 1];
            }
            float m = l[0]; int idx = 0;
#pragma unroll
            for (int c = 1; c < 10; c++) if (l[c] > m) { m = l[c]; idx = c; }
            float sum = 0.f;
#pragma unroll
            for (int c = 0; c < 10; c++) sum += __expf(l[c] - m);
            float lse = m + __logf(sum);
            int p = i * (1023 - i) / 2 + j - i - 1;
            float2* o2 = (float2*)(out + (size_t)p * 10);
#pragma unroll
            for (int q = 0; q < 5; q++)
                o2[q] = make_float2(l[2 * q] - lse, l[2 * q + 1] - lse);
            out[10 * PP + p] = (float)idx;
            float x = sv[s] + sbv;
            out[11 * PP + p] = 1.f / (1.f + __expf(-x));
        }
    }
}

extern "C" void kernel_launch(void* const* d_in, const int* in_sizes, int n_in,
                              void* d_out, int out_size) {
    (void)in_sizes; (void)n_in; (void)out_size;
    const float* features = (const float*)d_in[0];
    const float* cw1 = (const float*)d_in[1];
    const float* cb1 = (const float*)d_in[2];
    const float* cw2 = (const float*)d_in[3];
    const float* cb2 = (const float*)d_in[4];
    const float* sw1 = (const float*)d_in[5];
    const float* sb1 = (const float*)d_in[6];
    const float* sw2 = (const float*)d_in[7];
    const float* sb2 = (const float*)d_in[8];
    float* out = (float*)d_out;

    cudaFuncSetAttribute(pair_kernel, cudaFuncAttributeMaxDynamicSharedMemorySize,
                         SMEMF * sizeof(float));

    proj_gemm<<<dim3(48, 8), 128>>>(features, cw1, sw1);
    pair_kernel<<<136, 1024, SMEMF * sizeof(float)>>>(
        cb1, cw2, cb2, sb1, sw2, sb2, out);
}

// round 10
// speedup vs baseline: 2.6639x; 1.0003x over previous
#include <cuda_runtime.h>

#define NN 512
#define PP 130816
typedef unsigned long long ull;

__device__ float g_ca[NN*512];
__device__ float g_cb[NN*512];
__device__ float g_sa[NN*256];
__device__ float g_sb[NN*256];

__device__ __forceinline__ ull pack2(float lo, float hi) {
    ull r; asm("mov.b64 %0, {%1, %2};" : "=l"(r) : "f"(lo), "f"(hi)); return r;
}
__device__ __forceinline__ void fma2(ull& d, ull a, ull b) {
    asm("fma.rn.f32x2 %0, %1, %2, %0;" : "+l"(d) : "l"(a), "l"(b));
}
__device__ __forceinline__ ull add2(ull a, ull b) {
    ull r; asm("add.rn.f32x2 %0, %1, %2;" : "=l"(r) : "l"(a), "l"(b)); return r;
}
__device__ __forceinline__ float2 unpack2(ull v) {
    float2 f; asm("mov.b64 {%0, %1}, %2;" : "=f"(f.x), "=f"(f.y) : "l"(v)); return f;
}

// ---------------------------------------------------------------------------
// Phase 1: C = F(512x512) @ B(512 x 1536 concat). BM=64, BN=32, BK=32,
// 128 threads, grid (48,8), double-buffered (prefetch window > LDG latency).
// B staged duplicated as (b,b) ulls; A staged transposed.
// ---------------------------------------------------------------------------
__global__ __launch_bounds__(128) void proj_gemm(const float* __restrict__ F,
                                                 const float* __restrict__ cw1,
                                                 const float* __restrict__ sw1) {
    __shared__ __align__(16) float As[2][32 * 68];
    __shared__ __align__(16) ull  Bs[2][32 * 32];
    int t = threadIdx.x;
    int cglob = blockIdx.x * 32;
    const float* Bp; float* Cp; int ldb, bcol;
    if (cglob < 512)       { Bp = cw1;             Cp = g_ca; ldb = 512; bcol = cglob; }
    else if (cglob < 1024) { Bp = cw1 + 512 * 512; Cp = g_cb; ldb = 512; bcol = cglob - 512; }
    else if (cglob < 1280) { Bp = sw1;             Cp = g_sa; ldb = 256; bcol = cglob - 1024; }
    else                   { Bp = sw1 + 512 * 256; Cp = g_sb; ldb = 256; bcol = cglob - 1280; }
    int rb = blockIdx.y * 64;
    int rowg = t & 15, colg = t >> 4;

    ull acc[2][4];
#pragma unroll
    for (int a = 0; a < 2; a++)
#pragma unroll
        for (int b = 0; b < 4; b++) acc[a][b] = 0ull;

    float4 pa[4], pb[2];
#pragma unroll
    for (int it = 0; it < 4; it++) {
        int idx = t + it * 128, row = idx >> 3, q8 = idx & 7;
        pa[it] = *(const float4*)&F[(rb + row) * 512 + q8 * 4];
    }
#pragma unroll
    for (int it = 0; it < 2; it++) {
        int idx = t + it * 128, k = idx >> 3, q8 = idx & 7;
        pb[it] = *(const float4*)&Bp[k * ldb + bcol + q8 * 4];
    }
#pragma unroll
    for (int it = 0; it < 4; it++) {
        int idx = t + it * 128, row = idx >> 3, q8 = idx & 7;
        As[0][(q8 * 4 + 0) * 68 + row] = pa[it].x;
        As[0][(q8 * 4 + 1) * 68 + row] = pa[it].y;
        As[0][(q8 * 4 + 2) * 68 + row] = pa[it].z;
        As[0][(q8 * 4 + 3) * 68 + row] = pa[it].w;
    }
#pragma unroll
    for (int it = 0; it < 2; it++) {
        int idx = t + it * 128, k = idx >> 3, q8 = idx & 7;
        Bs[0][k * 32 + q8 * 4 + 0] = pack2(pb[it].x, pb[it].x);
        Bs[0][k * 32 + q8 * 4 + 1] = pack2(pb[it].y, pb[it].y);
        Bs[0][k * 32 + q8 * 4 + 2] = pack2(pb[it].z, pb[it].z);
        Bs[0][k * 32 + q8 * 4 + 3] = pack2(pb[it].w, pb[it].w);
    }
    __syncthreads();

    for (int tile = 0; tile < 16; tile++) {
        int cur = tile & 1;
        if (tile < 15) {
            int k0 = (tile + 1) * 32;
#pragma unroll
            for (int it = 0; it < 4; it++) {
                int idx = t + it * 128, row = idx >> 3, q8 = idx & 7;
                pa[it] = *(const float4*)&F[(rb + row) * 512 + k0 + q8 * 4];
            }
#pragma unroll
            for (int it = 0; it < 2; it++) {
                int idx = t + it * 128, k = idx >> 3, q8 = idx & 7;
                pb[it] = *(const float4*)&Bp[(k0 + k) * ldb + bcol + q8 * 4];
            }
        }
#pragma unroll
        for (int k = 0; k < 32; k++) {
            ulonglong2 aA = *(const ulonglong2*)&As[cur][k * 68 + rowg * 4];
            ulonglong2 b0 = *(const ulonglong2*)&Bs[cur][k * 32 + colg * 4];
            ulonglong2 b1 = *(const ulonglong2*)&Bs[cur][k * 32 + colg * 4 + 2];
            fma2(acc[0][0], aA.x, b0.x); fma2(acc[0][1], aA.x, b0.y);
            fma2(acc[0][2], aA.x, b1.x); fma2(acc[0][3], aA.x, b1.y);
            fma2(acc[1][0], aA.y, b0.x); fma2(acc[1][1], aA.y, b0.y);
            fma2(acc[1][2], aA.y, b1.x); fma2(acc[1][3], aA.y, b1.y);
        }
        if (tile < 15) {
            int nxt = cur ^ 1;
#pragma unroll
            for (int it = 0; it < 4; it++) {
                int idx = t + it * 128, row = idx >> 3, q8 = idx & 7;
                As[nxt][(q8 * 4 + 0) * 68 + row] = pa[it].x;
                As[nxt][(q8 * 4 + 1) * 68 + row] = pa[it].y;
                As[nxt][(q8 * 4 + 2) * 68 + row] = pa[it].z;
                As[nxt][(q8 * 4 + 3) * 68 + row] = pa[it].w;
            }
#pragma unroll
            for (int it = 0; it < 2; it++) {
                int idx = t + it * 128, k = idx >> 3, q8 = idx & 7;
                Bs[nxt][k * 32 + q8 * 4 + 0] = pack2(pb[it].x, pb[it].x);
                Bs[nxt][k * 32 + q8 * 4 + 1] = pack2(pb[it].y, pb[it].y);
                Bs[nxt][k * 32 + q8 * 4 + 2] = pack2(pb[it].z, pb[it].z);
                Bs[nxt][k * 32 + q8 * 4 + 3] = pack2(pb[it].w, pb[it].w);
            }
        }
        __syncthreads();
    }
#pragma unroll
    for (int mp = 0; mp < 2; mp++) {
        int r = rb + rowg * 4 + mp * 2;
#pragma unroll
        for (int n = 0; n < 4; n++) {
            float2 f = unpack2(acc[mp][n]);
            int c = bcol + colg * 4 + n;
            Cp[r * ldb + c] = f.x;
            Cp[(r + 1) * ldb + c] = f.y;
        }
    }
}

// ---------------------------------------------------------------------------
// Phase 2: tile 32j x 32i, 1024 threads = 32 warps (occ 50%), K-SPLIT:
// warps 0-15 (half=0) k<256, warps 16-31 (half=1) k>=256, same pairs.
// Warp group wg covers i = ibase+2wg, +1 (2 pairs/lane); lane = j.
// Class-paired accumulators: acc0[q]=(logit_{2q}, logit_{2q+1}) for i0, acc1 for i1.
// smem floats: bC 32x516 (cb1 folded) | aC [16][512][2] | w2 [512][12 pad].
// Strength overlays same regions; k-half reduction via smem at the end.
// ---------------------------------------------------------------------------
#define O_BC 0
#define O_AC 16512
#define O_WC 32896
#define SMEMF 39040

__global__ __launch_bounds__(1024) void pair_kernel(
    const float* __restrict__ cb1, const float* __restrict__ cw2,
    const float* __restrict__ cb2, const float* __restrict__ sb1,
    const float* __restrict__ sw2, const float* __restrict__ sb2,
    float* __restrict__ out)
{
    extern __shared__ float sm[];
    int bid = blockIdx.x;
    int jb = (int)((sqrtf(8.0f * bid + 1.0f) - 1.0f) * 0.5f);
    while ((jb + 1) * (jb + 2) / 2 <= bid) jb++;
    while (jb * (jb + 1) / 2 > bid) jb--;
    int ib = bid - jb * (jb + 1) / 2;
    int jbase = jb * 32, ibase = ib * 32;
    int t = threadIdx.x;
    int w = t >> 5, lane = t & 31;
    int wg = w & 15, half = w >> 4;

    // ---- stage classifier tables ----
#pragma unroll
    for (int it = 0; it < 4; it++) {          // bC rows (+cb1)
        int idx = t + it * 1024;
        int r = idx >> 7, q = (idx & 127) * 4;
        float4 vb = *(const float4*)&g_cb[(jbase + r) * 512 + q];
        float4 vc = *(const float4*)&cb1[q];
        vb.x += vc.x; vb.y += vc.y; vb.z += vc.z; vb.w += vc.w;
        *(float4*)&sm[O_BC + r * 516 + q] = vb;
    }
#pragma unroll
    for (int it = 0; it < 4; it++) {          // aC interleaved [wg][k][2]
        int idx = t + it * 1024;
        int r = idx >> 7, q = (idx & 127) * 4;
        float4 va = *(const float4*)&g_ca[(ibase + r) * 512 + q];
        float* dst = &sm[O_AC + (r >> 1) * 1024 + q * 2 + (r & 1)];
        dst[0] = va.x; dst[2] = va.y; dst[4] = va.z; dst[6] = va.w;
    }
    for (int idx = t; idx < 5120; idx += 1024) {   // w2 rows padded to 12
        int k = idx / 10, c = idx - k * 10;
        sm[O_WC + k * 12 + c] = cw2[idx];
    }
    __syncthreads();

    int j = jbase + lane;
    const float* bRow = &sm[O_BC + lane * 516];
    const float* aP   = &sm[O_AC + wg * 1024];

    ull acc0[5], acc1[5];
#pragma unroll
    for (int q = 0; q < 5; q++) { acc0[q] = 0ull; acc1[q] = 0ull; }

    int koff = half * 256;
    for (int k0 = koff; k0 < koff + 256; k0 += 4) {
        float4 bv = *(const float4*)(bRow + k0);
        ulonglong2 aA = *(const ulonglong2*)(aP + 2 * k0);
        ulonglong2 aB = *(const ulonglong2*)(aP + 2 * k0 + 4);
        ull ap[4] = {aA.x, aA.y, aB.x, aB.y};
        float bf[4] = {bv.x, bv.y, bv.z, bv.w};
#pragma unroll
        for (int kk = 0; kk < 4; kk++) {
            ull s = add2(ap[kk], pack2(bf[kk], bf[kk]));
            float2 f = unpack2(s);
            float h0 = fmaxf(f.x, 0.f), h1 = fmaxf(f.y, 0.f);
            ull hh0 = pack2(h0, h0), hh1 = pack2(h1, h1);
            const float* wr = &sm[O_WC + (k0 + kk) * 12];
            ulonglong2 w01 = *(const ulonglong2*)wr;
            ulonglong2 w23 = *(const ulonglong2*)(wr + 4);
            ull w4 = *(const ull*)(wr + 8);
            fma2(acc0[0], hh0, w01.x); fma2(acc0[1], hh0, w01.y);
            fma2(acc0[2], hh0, w23.x); fma2(acc0[3], hh0, w23.y);
            fma2(acc0[4], hh0, w4);
            fma2(acc1[0], hh1, w01.x); fma2(acc1[1], hh1, w01.y);
            fma2(acc1[2], hh1, w23.x); fma2(acc1[3], hh1, w23.y);
            fma2(acc1[4], hh1, w4);
        }
    }

    // ---- strength path: overlay same smem ----
    __syncthreads();
#pragma unroll
    for (int it = 0; it < 2; it++) {          // bS rows (+sb1), 32x260
        int idx = t + it * 1024;
        int r = idx >> 6, q = (idx & 63) * 4;
        float4 vb = *(const float4*)&g_sb[(jbase + r) * 256 + q];
        float4 vc = *(const float4*)&sb1[q];
        vb.x += vc.x; vb.y += vc.y; vb.z += vc.z; vb.w += vc.w;
        *(float4*)&sm[O_BC + r * 260 + q] = vb;
    }
#pragma unroll
    for (int it = 0; it < 2; it++) {          // aS interleaved [wg][k][2]
        int idx = t + it * 1024;
        int r = idx >> 6, q = (idx & 63) * 4;
        float4 va = *(const float4*)&g_sa[(ibase + r) * 256 + q];
        float* dst = &sm[O_AC + (r >> 1) * 512 + q * 2 + (r & 1)];
        dst[0] = va.x; dst[2] = va.y; dst[4] = va.z; dst[6] = va.w;
    }
    if (t < 256) sm[O_WC + t] = sw2[t];
    __syncthreads();

    float s0 = 0.f, s1 = 0.f;
    {
        const float* sbRow = &sm[O_BC + lane * 260];
        const float* saP   = &sm[O_AC + wg * 512];
        int koff2 = half * 128;
        for (int k0 = koff2; k0 < koff2 + 128; k0 += 4) {
            float4 bv = *(const float4*)(sbRow + k0);
            ulonglong2 aA = *(const ulonglong2*)(saP + 2 * k0);
            ulonglong2 aB = *(const ulonglong2*)(saP + 2 * k0 + 4);
            float4 wv = *(const float4*)&sm[O_WC + k0];
            ull ap[4] = {aA.x, aA.y, aB.x, aB.y};
            float bf[4] = {bv.x, bv.y, bv.z, bv.w};
            float wf[4] = {wv.x, wv.y, wv.z, wv.w};
#pragma unroll
            for (int kk = 0; kk < 4; kk++) {
                ull s = add2(ap[kk], pack2(bf[kk], bf[kk]));
                float2 f = unpack2(s);
                s0 = fmaf(fmaxf(f.x, 0.f), wf[kk], s0);
                s1 = fmaf(fmaxf(f.y, 0.f), wf[kk], s1);
            }
        }
    }

    // ---- k-half reduction ----
    __syncthreads();
    ull* red = (ull*)&sm[O_AC];
    int rbase = (wg * 11) * 32 + lane;
    if (half == 1) {
#pragma unroll
        for (int q = 0; q < 5; q++) {
            red[rbase + q * 32] = acc0[q];
            red[rbase + (5 + q) * 32] = acc1[q];
        }
        red[rbase + 10 * 32] = pack2(s0, s1);
    }
    __syncthreads();

    if (half == 0) {
#pragma unroll
        for (int q = 0; q < 5; q++) {
            acc0[q] = add2(acc0[q], red[rbase + q * 32]);
            acc1[q] = add2(acc1[q], red[rbase + (5 + q) * 32]);
        }
        float2 rs = unpack2(red[rbase + 10 * 32]);
        s0 += rs.x; s1 += rs.y;

        float b2[10];
#pragma unroll
        for (int c = 0; c < 10; c++) b2[c] = __ldg(&cb2[c]);
        float sbv = __ldg(&sb2[0]);
        float sv[2] = {s0, s1};
#pragma unroll
        for (int s = 0; s < 2; s++) {
            int i = ibase + 2 * wg + s;
            if (j <= i) continue;
            float l[10];
#pragma unroll
            for (int q = 0; q < 5; q++) {
                float2 f = unpack2(s ? acc1[q] : acc0[q]);
                l[2 * q] = f.x + b2[2 * q];
                l[2 * q + 1] = f.y + b2[2 * q + 1];
            }
            float m = l[0]; int idx = 0;
#pragma unroll
            for (int c = 1; c < 10; c++) if (l[c] > m) { m = l[c]; idx = c; }
            float sum = 0.f;
#pragma unroll
            for (int c = 0; c < 10; c++) sum += __expf(l[c] - m);
            float lse = m + __logf(sum);
            int p = i * (1023 - i) / 2 + j - i - 1;
            float2* o2 = (float2*)(out + (size_t)p * 10);
#pragma unroll
            for (int q = 0; q < 5; q++)
                o2[q] = make_float2(l[2 * q] - lse, l[2 * q + 1] - lse);
            out[10 * PP + p] = (float)idx;
            float x = sv[s] + sbv;
            out[11 * PP + p] = 1.f / (1.f + __expf(-x));
        }
    }
}

extern "C" void kernel_launch(void* const* d_in, const int* in_sizes, int n_in,
                              void* d_out, int out_size) {
    (void)in_sizes; (void)n_in; (void)out_size;
    const float* features = (const float*)d_in[0];
    const float* cw1 = (const float*)d_in[1];
    const float* cb1 = (const float*)d_in[2];
    const float* cw2 = (const float*)d_in[3];
    const float* cb2 = (const float*)d_in[4];
    const float* sw1 = (const float*)d_in[5];
    const float* sb1 = (const float*)d_in[6];
    const float* sw2 = (const float*)d_in[7];
    const float* sb2 = (const float*)d_in[8];
    float* out = (float*)d_out;

    cudaFuncSetAttribute(pair_kernel, cudaFuncAttributeMaxDynamicSharedMemorySize,
                         SMEMF * sizeof(float));

    proj_gemm<<<dim3(48, 8), 128>>>(features, cw1, sw1);
    pair_kernel<<<136, 1024, SMEMF * sizeof(float)>>>(
        cb1, cw2, cb2, sb1, sw2, sb2, out);
}